// round 9
// baseline (speedup 1.0000x reference)
#include <cuda_runtime.h>
#include <cuda_bf16.h>

#define NUM_POINTS 16
#define IN_CHANNELS 64
#define OUT_CHANNELS 256
#define NUM_STEPS 3
#define THREADS 128
#define WARPS_PER_BLOCK (THREADS / 32)
#define ROWS_PER_WARP 2

// Accurate fast tanh: t = 1 - 2/(exp(2x)+1), via ex2.approx (~2ulp) + rcp.approx (~1ulp).
__device__ __forceinline__ float tanh_fast(float x) {
    const float LOG2E_X2 = 2.8853900817779268f;  // 2*log2(e)
    float e, r;
    float z = x * LOG2E_X2;
    asm("ex2.approx.f32 %0, %1;" : "=f"(e) : "f"(z));
    float d = e + 1.0f;
    asm("rcp.approx.f32 %0, %1;" : "=f"(r) : "f"(d));
    return fmaf(-2.0f, r, 1.0f);
}

__device__ __forceinline__ float iterate_g(float x, const float2* __restrict__ lut) {
    // 8+8t in [0,16]; fmaf(t, 8, 8 + 1.5*2^23) deposits round-nearest-even
    // integer in the low mantissa bits (single rounding).
    const float MAGIC = 12582912.0f + 8.0f;  // 1.5*2^23 + 8
#pragma unroll
    for (int s = 0; s < NUM_STEPS; s++) {
        float t = tanh_fast(x);
        int pos = __float_as_int(fmaf(t, 8.0f, MAGIC)) & 31;
        pos = min(pos, NUM_POINTS - 1);
        float2 c = lut[pos];           // pre-scaled by 1/NUM_STEPS
        x = fmaf(t, c.y, x + c.x);
    }
    return x;
}

__global__ __launch_bounds__(THREADS) void functional_flow_kernel(
    const float* __restrict__ data,
    const float* __restrict__ angles,
    const float* __restrict__ velo,
    float* __restrict__ out) {
    // Per-warp private LUT: no block-wide barrier, warps fully independent.
    __shared__ float2 lut_all[WARPS_PER_BLOCK][NUM_POINTS];

    int tid  = threadIdx.x;
    int warp = tid >> 5;
    int lane = tid & 31;
    int half = lane >> 4;        // which of the warp's 2 rows
    int subl = lane & 15;        // lane within the 16-lane row group

    int row = (blockIdx.x * WARPS_PER_BLOCK + warp) * ROWS_PER_WARP + half;

    // Each lane: one float4 = 4 channels of its row (16 lanes cover 64 ch).
    const float4* dp = reinterpret_cast<const float4*>(data);
    float4 d = dp[row * (IN_CHANNELS / 4) + subl];

    float2* lut = lut_all[warp];
    if (lane < NUM_POINTS) {
        float a = angles[lane];
        float v = velo[lane] * (1.0f / (float)NUM_STEPS);
        lut[lane] = make_float2(v * __cosf(a), v * __sinf(a));
    }
    __syncwarp();

    // Four independent chains (ILP=4).
    float s = (iterate_g(d.x, lut) + iterate_g(d.y, lut)) +
              (iterate_g(d.z, lut) + iterate_g(d.w, lut));

    // Sum across the 16-lane row group (xor offsets stay within the half-warp).
#pragma unroll
    for (int off = 8; off > 0; off >>= 1)
        s += __shfl_xor_sync(0xFFFFFFFFu, s, off);

    // Broadcast row sum to 256 out channels: 16 floats/lane = 4x float4.
    float4 v4 = make_float4(s, s, s, s);
    float4* op = reinterpret_cast<float4*>(out) + (size_t)row * (OUT_CHANNELS / 4);
#pragma unroll
    for (int j = 0; j < 4; j++)
        op[j * 16 + subl] = v4;
}

extern "C" void kernel_launch(void* const* d_in, const int* in_sizes, int n_in,
                              void* d_out, int out_size) {
    const float* data   = (const float*)d_in[0];
    const float* angles = (const float*)d_in[1];
    const float* velo   = (const float*)d_in[2];
    float* out = (float*)d_out;

    int nrows = in_sizes[0] / IN_CHANNELS;               // 4096
    int rows_per_block = WARPS_PER_BLOCK * ROWS_PER_WARP; // 8
    int blocks = (nrows + rows_per_block - 1) / rows_per_block;  // 512

    functional_flow_kernel<<<blocks, THREADS>>>(data, angles, velo, out);
}

// round 12
// speedup vs baseline: 1.0048x; 1.0048x over previous
#include <cuda_runtime.h>
#include <cuda_bf16.h>

#define NUM_POINTS 16
#define IN_CHANNELS 64
#define OUT_CHANNELS 256
#define NUM_STEPS 3
#define THREADS 256
#define WARPS_PER_BLOCK (THREADS / 32)
#define ROWS_PER_WARP 2

// Accurate fast tanh: t = 1 - 2/(exp(2x)+1), via ex2.approx (~2ulp) + rcp.approx (~1ulp).
__device__ __forceinline__ float tanh_fast(float x) {
    const float LOG2E_X2 = 2.8853900817779268f;  // 2*log2(e)
    float e, r;
    float z = x * LOG2E_X2;
    asm("ex2.approx.f32 %0, %1;" : "=f"(e) : "f"(z));
    float d = e + 1.0f;
    asm("rcp.approx.f32 %0, %1;" : "=f"(r) : "f"(d));
    return fmaf(-2.0f, r, 1.0f);
}

// LUT lives in registers across lanes: lane i holds entry (i & 15).
// Lookup = two independent warp shuffles on the bin index.
__device__ __forceinline__ float iterate_g(float x, float l0, float l1) {
    // 8+8t in [0,16]; fmaf(t, 8, 8 + 1.5*2^23) deposits round-nearest-even
    // integer in the low mantissa bits (single rounding).
    const float MAGIC = 12582912.0f + 8.0f;  // 1.5*2^23 + 8
#pragma unroll
    for (int s = 0; s < NUM_STEPS; s++) {
        float t = tanh_fast(x);
        int pos = __float_as_int(fmaf(t, 8.0f, MAGIC)) & 31;
        pos = min(pos, NUM_POINTS - 1);
        float c0 = __shfl_sync(0xFFFFFFFFu, l0, pos);
        float c1 = __shfl_sync(0xFFFFFFFFu, l1, pos);
        x = fmaf(t, c1, x + c0);
    }
    return x;
}

__global__ __launch_bounds__(THREADS) void functional_flow_kernel(
    const float* __restrict__ data,
    const float* __restrict__ angles,
    const float* __restrict__ velo,
    float* __restrict__ out) {
    int tid  = threadIdx.x;
    int warp = tid >> 5;
    int lane = tid & 31;
    int half = lane >> 4;        // which of the warp's 2 rows
    int subl = lane & 15;        // lane within the 16-lane row group

    int row = (blockIdx.x * WARPS_PER_BLOCK + warp) * ROWS_PER_WARP + half;

    // Each lane: one float4 = 4 channels of its row (16 lanes cover 64 ch).
    const float4* dp = reinterpret_cast<const float4*>(data);
    float4 d = dp[row * (IN_CHANNELS / 4) + subl];

    // Register LUT entry for this lane (replicated across both half-warps).
    float a = angles[subl];
    float v = velo[subl] * (1.0f / (float)NUM_STEPS);
    float l0 = v * __cosf(a);
    float l1 = v * __sinf(a);

    // Four independent chains (ILP=4), zero smem, zero barriers.
    float s = (iterate_g(d.x, l0, l1) + iterate_g(d.y, l0, l1)) +
              (iterate_g(d.z, l0, l1) + iterate_g(d.w, l0, l1));

    // Sum across the 16-lane row group (xor offsets stay within the half-warp).
#pragma unroll
    for (int off = 8; off > 0; off >>= 1)
        s += __shfl_xor_sync(0xFFFFFFFFu, s, off);

    // Broadcast row sum to 256 out channels: 16 floats/lane = 4x float4.
    float4 v4 = make_float4(s, s, s, s);
    float4* op = reinterpret_cast<float4*>(out) + (size_t)row * (OUT_CHANNELS / 4);
#pragma unroll
    for (int j = 0; j < 4; j++)
        op[j * 16 + subl] = v4;
}

extern "C" void kernel_launch(void* const* d_in, const int* in_sizes, int n_in,
                              void* d_out, int out_size) {
    const float* data   = (const float*)d_in[0];
    const float* angles = (const float*)d_in[1];
    const float* velo   = (const float*)d_in[2];
    float* out = (float*)d_out;

    int nrows = in_sizes[0] / IN_CHANNELS;                 // 4096
    int rows_per_block = WARPS_PER_BLOCK * ROWS_PER_WARP;  // 16
    int blocks = (nrows + rows_per_block - 1) / rows_per_block;  // 256

    functional_flow_kernel<<<blocks, THREADS>>>(data, angles, velo, out);
}